// round 2
// baseline (speedup 1.0000x reference)
#include <cuda_runtime.h>

#define N_NODES 50000
#define N_EDGES 800000
#define HD_SCALE 0.17677669529663687f   // 1/sqrt(32)

// ---------------- scratch (device globals: no allocation allowed) ----------
__device__ __align__(256) float g_Q[N_NODES * 128];
__device__ __align__(256) float g_K[N_NODES * 128];
__device__ __align__(256) float g_V[N_NODES * 128];
__device__ __align__(256) float g_attn[N_EDGES * 4];
__device__ __align__(256) float g_sum[N_NODES * 4];
__device__ __align__(256) float g_agg[N_NODES * 128];
__device__ __align__(256) float g_Wf[128 * 128];
__device__ __align__(256) float g_bf[128];
__device__ unsigned g_maxbits;

// ---------------- init: zero accumulators, set max to -inf -----------------
__global__ void k_init() {
    int i = blockIdx.x * blockDim.x + threadIdx.x;
    if (i < N_NODES * 128) g_agg[i] = 0.f;
    if (i < N_NODES * 4) g_sum[i] = 0.f;
    if (i == 0) g_maxbits = 0xFF800000u;   // bits of -inf
}

// ---------------- fuse Wo into Wm lower half --------------------------------
// g_Wf = Wo @ Wm[128:256], g_bf = bo @ Wm[128:256] + bm
__global__ void k_fusew(const float* __restrict__ Wo, const float* __restrict__ Wm,
                        const float* __restrict__ bo, const float* __restrict__ bm) {
    int r = blockIdx.x;        // 0..127
    int j = threadIdx.x;       // 0..127
    float acc = 0.f;
    #pragma unroll 8
    for (int k = 0; k < 128; k++)
        acc += Wo[r * 128 + k] * Wm[(128 + k) * 128 + j];
    g_Wf[r * 128 + j] = acc;
    if (r == 0) {
        float b = bm[j];
        #pragma unroll 8
        for (int k = 0; k < 128; k++)
            b += bo[k] * Wm[(128 + k) * 128 + j];
        g_bf[j] = b;
    }
}

// ---------------- QKV GEMM: [N,128] @ [128,128] x3 --------------------------
// 64 rows x 128 cols per block, 256 threads, 4x8 register tile per thread.
__global__ __launch_bounds__(256) void k_qkv(const float* __restrict__ x,
                                             const float* __restrict__ Wq,
                                             const float* __restrict__ Wk,
                                             const float* __restrict__ Wv) {
    const float* W;
    float* out;
    if (blockIdx.y == 0)      { W = Wq; out = g_Q; }
    else if (blockIdx.y == 1) { W = Wk; out = g_K; }
    else                      { W = Wv; out = g_V; }

    int rg = threadIdx.x >> 4;                 // 0..15
    int c0 = (threadIdx.x & 15) * 8;           // 0..120
    int r0 = blockIdx.x * 64 + rg * 4;

    int rr[4];
    #pragma unroll
    for (int r = 0; r < 4; r++) {
        int ri = r0 + r;
        rr[r] = ri < N_NODES ? ri : (N_NODES - 1);
    }

    float acc[4][8];
    #pragma unroll
    for (int r = 0; r < 4; r++)
        #pragma unroll
        for (int c = 0; c < 8; c++) acc[r][c] = 0.f;

    #pragma unroll 4
    for (int k = 0; k < 128; k++) {
        float4 w0 = *(const float4*)(W + k * 128 + c0);
        float4 w1 = *(const float4*)(W + k * 128 + c0 + 4);
        float xv[4];
        #pragma unroll
        for (int r = 0; r < 4; r++) xv[r] = x[(size_t)rr[r] * 128 + k];
        #pragma unroll
        for (int r = 0; r < 4; r++) {
            acc[r][0] = fmaf(xv[r], w0.x, acc[r][0]);
            acc[r][1] = fmaf(xv[r], w0.y, acc[r][1]);
            acc[r][2] = fmaf(xv[r], w0.z, acc[r][2]);
            acc[r][3] = fmaf(xv[r], w0.w, acc[r][3]);
            acc[r][4] = fmaf(xv[r], w1.x, acc[r][4]);
            acc[r][5] = fmaf(xv[r], w1.y, acc[r][5]);
            acc[r][6] = fmaf(xv[r], w1.z, acc[r][6]);
            acc[r][7] = fmaf(xv[r], w1.w, acc[r][7]);
        }
    }

    #pragma unroll
    for (int r = 0; r < 4; r++) {
        if (r0 + r < N_NODES) {
            float4* o = (float4*)(out + (size_t)(r0 + r) * 128 + c0);
            o[0] = make_float4(acc[r][0], acc[r][1], acc[r][2], acc[r][3]);
            o[1] = make_float4(acc[r][4], acc[r][5], acc[r][6], acc[r][7]);
        }
    }
}

// ---------------- attention logits + global max ------------------------------
// edge_index is int32 (JAX silently downcasts int64 without x64 enabled)
__global__ __launch_bounds__(256) void k_attn(const int* __restrict__ ei,
                                              const float* __restrict__ ea,
                                              const float* __restrict__ We) {
    int idx = blockIdx.x * 256 + threadIdx.x;
    float a = -3.4e38f;
    if (idx < N_EDGES * 4) {
        int e = idx >> 2, h = idx & 3;
        int src = ei[e];
        int dst = ei[N_EDGES + e];
        const float4* q = (const float4*)(g_Q + (size_t)dst * 128 + h * 32);
        const float4* kk = (const float4*)(g_K + (size_t)src * 128 + h * 32);
        float acc = 0.f;
        #pragma unroll
        for (int i = 0; i < 8; i++) {
            float4 qa = q[i], kb = kk[i];
            acc += qa.x * kb.x + qa.y * kb.y + qa.z * kb.z + qa.w * kb.w;
        }
        float b = ea[e * 3 + 0] * We[0 * 4 + h]
                + ea[e * 3 + 1] * We[1 * 4 + h]
                + ea[e * 3 + 2] * We[2 * 4 + h];
        a = acc * HD_SCALE + b;
        a = a >= 0.f ? a : 0.2f * a;        // leaky_relu(0.2)
        g_attn[idx] = a;
    }
    // block max -> single atomic
    __shared__ float smax[8];
    #pragma unroll
    for (int o = 16; o; o >>= 1) a = fmaxf(a, __shfl_xor_sync(0xffffffffu, a, o));
    if ((threadIdx.x & 31) == 0) smax[threadIdx.x >> 5] = a;
    __syncthreads();
    if (threadIdx.x < 8) {
        a = smax[threadIdx.x];
        #pragma unroll
        for (int o = 4; o; o >>= 1) a = fmaxf(a, __shfl_xor_sync(0xFFu, a, o));
        if (threadIdx.x == 0) {
            if (a >= 0.f) atomicMax((int*)&g_maxbits, __float_as_int(a));
            else          atomicMin(&g_maxbits, __float_as_uint(a));
        }
    }
}

// ---------------- exp + per-(dst,head) segment sum ---------------------------
__global__ __launch_bounds__(256) void k_expsum(const int* __restrict__ ei) {
    int idx = blockIdx.x * 256 + threadIdx.x;
    if (idx >= N_EDGES * 4) return;
    int e = idx >> 2, h = idx & 3;
    float gmax = __uint_as_float(g_maxbits);
    float ex = expf(g_attn[idx] - gmax);
    int dst = ei[N_EDGES + e];
    atomicAdd(&g_sum[dst * 4 + h], ex);
}

// ---------------- weighted-V scatter (warp per edge, red.v4) -----------------
__global__ __launch_bounds__(256) void k_scatter(const int* __restrict__ ei) {
    int e = blockIdx.x * 8 + (threadIdx.x >> 5);
    if (e >= N_EDGES) return;
    int lane = threadIdx.x & 31;
    int src = ei[e];
    int dst = ei[N_EDGES + e];
    int h = lane >> 3;
    float gmax = __uint_as_float(g_maxbits);
    float ex = expf(g_attn[e * 4 + h] - gmax);
    float s = g_sum[dst * 4 + h];
    float w = ex / fmaxf(s, 1e-12f);
    float4 v = ((const float4*)(g_V + (size_t)src * 128))[lane];
    float* p = g_agg + (size_t)dst * 128 + lane * 4;
    asm volatile("red.global.add.v4.f32 [%0], {%1, %2, %3, %4};"
                 :: "l"(p), "f"(v.x * w), "f"(v.y * w), "f"(v.z * w), "f"(v.w * w)
                 : "memory");
}

// ---------------- output GEMM: relu(x@Wm_x + agg@Wf + bf) --------------------
__global__ __launch_bounds__(256) void k_out(const float* __restrict__ x,
                                             const float* __restrict__ Wm,
                                             float* __restrict__ out) {
    int rg = threadIdx.x >> 4;
    int c0 = (threadIdx.x & 15) * 8;
    int r0 = blockIdx.x * 64 + rg * 4;

    int rr[4];
    #pragma unroll
    for (int r = 0; r < 4; r++) {
        int ri = r0 + r;
        rr[r] = ri < N_NODES ? ri : (N_NODES - 1);
    }

    float acc[4][8];
    #pragma unroll
    for (int r = 0; r < 4; r++)
        #pragma unroll
        for (int c = 0; c < 8; c++) acc[r][c] = 0.f;

    #pragma unroll 4
    for (int k = 0; k < 128; k++) {
        float4 w0 = *(const float4*)(Wm + k * 128 + c0);
        float4 w1 = *(const float4*)(Wm + k * 128 + c0 + 4);
        float xv[4];
        #pragma unroll
        for (int r = 0; r < 4; r++) xv[r] = x[(size_t)rr[r] * 128 + k];
        #pragma unroll
        for (int r = 0; r < 4; r++) {
            acc[r][0] = fmaf(xv[r], w0.x, acc[r][0]);
            acc[r][1] = fmaf(xv[r], w0.y, acc[r][1]);
            acc[r][2] = fmaf(xv[r], w0.z, acc[r][2]);
            acc[r][3] = fmaf(xv[r], w0.w, acc[r][3]);
            acc[r][4] = fmaf(xv[r], w1.x, acc[r][4]);
            acc[r][5] = fmaf(xv[r], w1.y, acc[r][5]);
            acc[r][6] = fmaf(xv[r], w1.z, acc[r][6]);
            acc[r][7] = fmaf(xv[r], w1.w, acc[r][7]);
        }
    }

    #pragma unroll 4
    for (int k = 0; k < 128; k++) {
        float4 w0 = *(const float4*)(g_Wf + k * 128 + c0);
        float4 w1 = *(const float4*)(g_Wf + k * 128 + c0 + 4);
        float av[4];
        #pragma unroll
        for (int r = 0; r < 4; r++) av[r] = g_agg[(size_t)rr[r] * 128 + k];
        #pragma unroll
        for (int r = 0; r < 4; r++) {
            acc[r][0] = fmaf(av[r], w0.x, acc[r][0]);
            acc[r][1] = fmaf(av[r], w0.y, acc[r][1]);
            acc[r][2] = fmaf(av[r], w0.z, acc[r][2]);
            acc[r][3] = fmaf(av[r], w0.w, acc[r][3]);
            acc[r][4] = fmaf(av[r], w1.x, acc[r][4]);
            acc[r][5] = fmaf(av[r], w1.y, acc[r][5]);
            acc[r][6] = fmaf(av[r], w1.z, acc[r][6]);
            acc[r][7] = fmaf(av[r], w1.w, acc[r][7]);
        }
    }

    float4 b0 = *(const float4*)(g_bf + c0);
    float4 b1 = *(const float4*)(g_bf + c0 + 4);
    #pragma unroll
    for (int r = 0; r < 4; r++) {
        if (r0 + r < N_NODES) {
            float4* o = (float4*)(out + (size_t)(r0 + r) * 128 + c0);
            o[0] = make_float4(fmaxf(acc[r][0] + b0.x, 0.f), fmaxf(acc[r][1] + b0.y, 0.f),
                               fmaxf(acc[r][2] + b0.z, 0.f), fmaxf(acc[r][3] + b0.w, 0.f));
            o[1] = make_float4(fmaxf(acc[r][4] + b1.x, 0.f), fmaxf(acc[r][5] + b1.y, 0.f),
                               fmaxf(acc[r][6] + b1.z, 0.f), fmaxf(acc[r][7] + b1.w, 0.f));
        }
    }
}

// ---------------- launch ------------------------------------------------------
extern "C" void kernel_launch(void* const* d_in, const int* in_sizes, int n_in,
                              void* d_out, int out_size) {
    const float* x  = (const float*)d_in[0];
    const int*   ei = (const int*)d_in[1];
    const float* ea = (const float*)d_in[2];
    const float* Wq = (const float*)d_in[3];
    const float* Wk = (const float*)d_in[4];
    const float* Wv = (const float*)d_in[5];
    const float* We = (const float*)d_in[6];
    const float* Wo = (const float*)d_in[7];
    const float* bo = (const float*)d_in[8];
    const float* Wm = (const float*)d_in[9];
    const float* bm = (const float*)d_in[10];
    float* out = (float*)d_out;

    k_init<<<(N_NODES * 128 + 255) / 256, 256>>>();
    k_fusew<<<128, 128>>>(Wo, Wm, bo, bm);
    k_qkv<<<dim3((N_NODES + 63) / 64, 3), 256>>>(x, Wq, Wk, Wv);
    k_attn<<<(N_EDGES * 4 + 255) / 256, 256>>>(ei, ea, We);
    k_expsum<<<(N_EDGES * 4 + 255) / 256, 256>>>(ei);
    k_scatter<<<(N_EDGES + 7) / 8, 256>>>(ei);
    k_out<<<(N_NODES + 63) / 64, 256>>>(x, Wm, out);
}